// round 8
// baseline (speedup 1.0000x reference)
#include <cuda_runtime.h>
#include <cuda_bf16.h>
#include <math.h>
#include <stdint.h>

#define B_ 32
#define T_ 2048
#define D_ 512
#define U_ 512
#define MT 65536            // B*T rows
#define MB_ 512             // M blocks of 128
#define NB_ 4               // N blocks of 128
#define KCI 4               // k chunks of 128 (int8)
#define STAGES 3
#define KSPLIT 8
#define TILE_I8 16384       // 128 rows x 128 int8
#define GRID_P 148
#define NTILES (MB_ * NB_)  // 2048

// ---------------- scratch (static device memory only) -----------------------
// int8 operands stored TILED+SWIZZLED (exact smem image), 16-bit split hi/lo.
__device__ __align__(128) char g_a1[MT * D_];
__device__ __align__(128) char g_a0[MT * D_];
__device__ __align__(128) char g_b1[U_ * D_];
__device__ __align__(128) char g_b0[U_ * D_];
__device__ float g_scaleA[MT];
__device__ float g_scaleB[U_];
__device__ float g_bias_part[KSPLIT][B_ * U_];
__device__ float g_part[NB_][MT];

// ---------------- PTX helpers -----------------------------------------------
__device__ __forceinline__ uint32_t smem_u32(const void* p) {
    uint32_t a;
    asm("{ .reg .u64 t; cvta.to.shared.u64 t, %1; cvt.u32.u64 %0, t; }"
        : "=r"(a) : "l"(p));
    return a;
}
__device__ __forceinline__ uint32_t sw128(uint32_t off) {
    return off ^ ((off >> 3) & 0x70);
}
#define MBAR_INIT(a, n) \
    asm volatile("mbarrier.init.shared.b64 [%0], %1;" :: "r"(a), "r"(n) : "memory")
#define MBAR_ARRIVE(a) \
    asm volatile("mbarrier.arrive.shared.b64 _, [%0];" :: "r"(a) : "memory")
#define MBAR_EXPECT_TX(a, n) \
    asm volatile("mbarrier.arrive.expect_tx.shared.b64 _, [%0], %1;" \
                 :: "r"(a), "r"(n) : "memory")
#define MBAR_WAIT(a, ph) do {                                                  \
    uint32_t _m = (a), _p = (ph), _d;                                          \
    asm volatile("{ .reg .pred p; mbarrier.try_wait.parity.acquire.cta.shared::cta.b64 p, [%1], %2; selp.b32 %0,1,0,p; }" \
                 : "=r"(_d) : "r"(_m), "r"(_p) : "memory");                    \
    if (!_d) {                                                                 \
        asm volatile("{ .reg .pred P1; WL%=: mbarrier.try_wait.parity.acquire.cta.shared::cta.b64 P1, [%0], %1, 0x989680; @P1 bra.uni WD%=; bra.uni WL%=; WD%=: }" \
                     :: "r"(_m), "r"(_p) : "memory");                          \
    }                                                                          \
} while (0)
#define BULK_G2S(dst, src, bytes, mbar)                                        \
    asm volatile("cp.async.bulk.shared::cluster.global.mbarrier::complete_tx::bytes [%0], [%1], %2, [%3];" \
                 :: "r"(dst), "l"(src), "r"(bytes), "r"(mbar) : "memory")
#define LDSM4(r, addr)                                                         \
    asm volatile("ldmatrix.sync.aligned.m8n8.x4.shared.b16 {%0,%1,%2,%3}, [%4];" \
                 : "=r"((r)[0]), "=r"((r)[1]), "=r"((r)[2]), "=r"((r)[3])      \
                 : "r"(addr))
#define IMMA16832(d, a, b)                                                     \
    asm volatile("mma.sync.aligned.m16n8k32.row.col.s32.s8.s8.s32 "            \
                 "{%0,%1,%2,%3}, {%4,%5,%6,%7}, {%8,%9}, {%0,%1,%2,%3};"       \
                 : "+r"((d)[0]), "+r"((d)[1]), "+r"((d)[2]), "+r"((d)[3])      \
                 : "r"((a)[0]), "r"((a)[1]), "r"((a)[2]), "r"((a)[3]),         \
                   "r"((b)[0]), "r"((b)[1]))

// tanh via exp: abs err ~1e-6; saturates correctly for large |x|
__device__ __forceinline__ float tanh_fast(float x) {
    float z = __expf(2.0f * x);
    return 1.0f - __fdividef(2.0f, z + 1.0f);
}

// quantize 16 floats -> hi/lo s8 granules (16-bit split, A = A1*256 + A0)
__device__ __forceinline__ void quant16(const float* f, float inv,
                                        uint4* hi, uint4* lo) {
    union { char c[16]; uint4 u; } p1, p0;
#pragma unroll
    for (int e = 0; e < 16; ++e) {
        int q = __float2int_rn(f[e] * inv);
        q = min(32512, max(-32512, q));
        int h = (q + 128) >> 8;
        p1.c[e] = (char)h;
        p0.c[e] = (char)(q - (h << 8));
    }
    *hi = p1.u;
    *lo = p0.u;
}

// ---------------- kernel 1a: value fp32 -> int8 hi/lo, tiled swizzled -------
// one warp per row; lane owns 16 contiguous k (one 16B granule per matrix)
__global__ void convert_value(const float4* __restrict__ v4) {
    const int m = blockIdx.x * 8 + (threadIdx.x >> 5);
    const int lane = threadIdx.x & 31;
    float f[16];
#pragma unroll
    for (int j = 0; j < 4; ++j) {
        float4 x = v4[(size_t)m * 128 + lane * 4 + j];
        f[4 * j] = x.x; f[4 * j + 1] = x.y; f[4 * j + 2] = x.z; f[4 * j + 3] = x.w;
    }
    float mx = 0.f;
#pragma unroll
    for (int e = 0; e < 16; ++e) mx = fmaxf(mx, fabsf(f[e]));
#pragma unroll
    for (int off = 16; off > 0; off >>= 1)
        mx = fmaxf(mx, __shfl_xor_sync(0xFFFFFFFFu, mx, off));
    mx = fmaxf(mx, 1e-30f);
    if (lane == 0) g_scaleA[m] = mx * (1.0f / 32512.f);
    const float inv = 32512.f / mx;

    uint4 hi, lo;
    quant16(f, inv, &hi, &lo);
    const int k0 = lane * 16;
    const int mb = m >> 7, r = m & 127;
    const size_t dest = (size_t)(mb * KCI + (k0 >> 7)) * TILE_I8 +
                        sw128((uint32_t)(r * 128 + (k0 & 127)));
    *reinterpret_cast<uint4*>(g_a1 + dest) = hi;
    *reinterpret_cast<uint4*>(g_a0 + dest) = lo;
}

// ---------------- kernel 1b: W1 [k][u] -> transposed int8 hi/lo tiled -------
// block = 32 u columns x full K. smem staged; per-column max then quantize.
__global__ void convert_w1t(const float* __restrict__ W1) {
    extern __shared__ float s[];                 // [512][33]
    __shared__ float red[32][8];
    __shared__ float sinv[32];
    const int t = threadIdx.x;                   // 256
    const int u0 = blockIdx.x * 32;
    const int ul = t & 31, seg = t >> 5;

    for (int i = 0; i < 64; ++i) {
        int k = seg + 8 * i;
        s[k * 33 + ul] = W1[(size_t)k * U_ + u0 + ul];
    }
    __syncthreads();

    {
        float mx = 0.f;
        for (int k = seg * 64; k < seg * 64 + 64; ++k)
            mx = fmaxf(mx, fabsf(s[k * 33 + ul]));
        red[ul][seg] = mx;
    }
    __syncthreads();
    if (t < 32) {
        float mx = red[t][0];
#pragma unroll
        for (int p = 1; p < 8; ++p) mx = fmaxf(mx, red[t][p]);
        mx = fmaxf(mx, 1e-30f);
        g_scaleB[u0 + t] = mx * (1.0f / 32512.f);
        sinv[t] = 32512.f / mx;
    }
    __syncthreads();

    const int u = u0 + ul;
    const int nb = u >> 7, r = u & 127;
    const float inv = sinv[ul];
#pragma unroll
    for (int i = 0; i < 4; ++i) {
        int g = seg + 8 * i;
        int k0 = g * 16;
        float f[16];
#pragma unroll
        for (int e = 0; e < 16; ++e) f[e] = s[(k0 + e) * 33 + ul];
        uint4 hi, lo;
        quant16(f, inv, &hi, &lo);
        size_t dest = (size_t)(nb * KCI + (k0 >> 7)) * TILE_I8 +
                      sw128((uint32_t)(r * 128 + (k0 & 127)));
        *reinterpret_cast<uint4*>(g_b1 + dest) = hi;
        *reinterpret_cast<uint4*>(g_b0 + dest) = lo;
    }
}

// ---------------- kernel 2: bias partials (split-K, deterministic) ----------
__global__ void bias_part_kernel(const float* __restrict__ q,
                                 const float* __restrict__ W2) {
    const int b = blockIdx.x, ks = blockIdx.y, u = threadIdx.x;
    const float* qb = q + b * D_;
    float acc = 0.f;
#pragma unroll 4
    for (int d = ks * (D_ / KSPLIT); d < (ks + 1) * (D_ / KSPLIT); ++d)
        acc = fmaf(qb[d], W2[(size_t)d * U_ + u], acc);
    g_bias_part[ks][b * U_ + u] = acc;
}

// ---------------- kernel 3: persistent IMMA GEMM + fused epilogue -----------
// grid = 148.  512 threads = 16 warps (wm 0-3 x wn 0-3), warp tile 32x32.
// K chunks of 128 int8 (4 per tile); 3-stage bulk pipeline across tiles.
// stage: A1(16K) A0(16K) B1(16K) B0(16K) = 64KB
#define SM_DATA 8192
#define STG_SZ 65536
#define SMEM_TOTAL (SM_DATA + STAGES * STG_SZ)

static __device__ __forceinline__ void produce_chunk(uint32_t sb, int bid, int cc) {
    const int t  = bid + (cc >> 2) * GRID_P;
    const int mb = t >> 2, nb = t & 3, c = cc & 3;
    const int s  = cc % STAGES;
    const uint32_t st = sb + SM_DATA + s * STG_SZ;
    const size_t offA = (size_t)(mb * KCI + c) * TILE_I8;
    const size_t offB = (size_t)(nb * KCI + c) * TILE_I8;
    MBAR_EXPECT_TX(sb + s * 16, 4 * TILE_I8);
    BULK_G2S(st,         g_a1 + offA, TILE_I8, sb + s * 16);
    BULK_G2S(st + 16384, g_a0 + offA, TILE_I8, sb + s * 16);
    BULK_G2S(st + 32768, g_b1 + offB, TILE_I8, sb + s * 16);
    BULK_G2S(st + 49152, g_b0 + offB, TILE_I8, sb + s * 16);
}

__global__ void __launch_bounds__(512, 1)
score_mma_kernel(const float* __restrict__ Vw) {
    extern __shared__ char smem[];
    const uint32_t sb = smem_u32(smem);
    const int tid = threadIdx.x;
    const int lane = tid & 31, wid = tid >> 5;
    const int wm = wid >> 2, wn = wid & 3;
    const int bid = blockIdx.x;

    const int ntiles  = (NTILES - bid + GRID_P - 1) / GRID_P;
    const int totalcc = ntiles * KCI;

    if (tid == 0) {
#pragma unroll
        for (int s = 0; s < STAGES; ++s) {
            MBAR_INIT(sb + s * 16, 1);
            MBAR_INIT(sb + s * 16 + 8, 16);
        }
    }
    __syncthreads();

    if (tid == 0) {
#pragma unroll
        for (int c = 0; c < STAGES; ++c)
            if (c < totalcc) produce_chunk(sb, bid, c);
    }

    uint32_t rowA[2], xmA[2], rowB[2], xmB[2];
#pragma unroll
    for (int mt = 0; mt < 2; ++mt) {
        rowA[mt] = (uint32_t)((wm * 32 + mt * 16 + (lane & 15)) * 128);
        xmA[mt]  = (rowA[mt] >> 3) & 0x70;
    }
#pragma unroll
    for (int p = 0; p < 2; ++p) {
        rowB[p] = (uint32_t)((wn * 32 + p * 16 + (lane & 15)) * 128);
        xmB[p]  = (rowB[p] >> 3) & 0x70;
    }
    const uint32_t hi16 = (uint32_t)(((lane >> 4) & 1) * 16);

    float4* sBVS = reinterpret_cast<float4*>(smem + 64);   // bias, V, sB
    float* red   = reinterpret_cast<float*>(smem + 64 + 2048);  // [128][4]

    int cc = 0;
    for (int j = 0; j < ntiles; ++j) {
        const int t  = bid + j * GRID_P;
        const int mb = t >> 2, nb = t & 3;
        const int m0 = mb * 128;
        const int b  = mb >> 4;

        if (tid < 128) {
            int u = nb * 128 + tid;
            float bs = 0.f;
#pragma unroll
            for (int jj = 0; jj < KSPLIT; ++jj) bs += g_bias_part[jj][b * U_ + u];
            sBVS[tid] = make_float4(bs, Vw[u], g_scaleB[u], 0.f);
        }
        // per-row A scales for this tile
        float sAr[2][2];
#pragma unroll
        for (int mt = 0; mt < 2; ++mt) {
            int base = m0 + wm * 32 + mt * 16 + (lane >> 2);
            sAr[mt][0] = g_scaleA[base];
            sAr[mt][1] = g_scaleA[base + 8];
        }
        __syncthreads();

        int hi[2][4][4], mi[2][4][4];
#pragma unroll
        for (int mt = 0; mt < 2; ++mt)
#pragma unroll
            for (int nt = 0; nt < 4; ++nt)
#pragma unroll
                for (int e = 0; e < 4; ++e) { hi[mt][nt][e] = 0; mi[mt][nt][e] = 0; }

#pragma unroll
        for (int c = 0; c < KCI; ++c, ++cc) {
            const int s = cc % STAGES;
            const uint32_t par = (uint32_t)((cc / STAGES) & 1);
            MBAR_WAIT(sb + s * 16, par);

            const uint32_t aBase = sb + SM_DATA + s * STG_SZ;
            const uint32_t bBase = aBase + 32768;
#pragma unroll
            for (int kk = 0; kk < 4; ++kk) {
                const uint32_t col = (uint32_t)(kk * 32) + hi16;
                uint32_t a1f[2][4], a0f[2][4], b1f[4][2], b0f[4][2];
#pragma unroll
                for (int mt = 0; mt < 2; ++mt) {
                    uint32_t ad = aBase + rowA[mt] + (col ^ xmA[mt]);
                    LDSM4(a1f[mt], ad);
                    LDSM4(a0f[mt], ad + 16384);
                }
#pragma unroll
                for (int p = 0; p < 2; ++p) {
                    uint32_t bd = bBase + rowB[p] + (col ^ xmB[p]);
                    uint32_t r[4];
                    LDSM4(r, bd);
                    b1f[2 * p][0] = r[0]; b1f[2 * p + 1][0] = r[1];
                    b1f[2 * p][1] = r[2]; b1f[2 * p + 1][1] = r[3];
                    LDSM4(r, bd + 16384);
                    b0f[2 * p][0] = r[0]; b0f[2 * p + 1][0] = r[1];
                    b0f[2 * p][1] = r[2]; b0f[2 * p + 1][1] = r[3];
                }
#pragma unroll
                for (int mt = 0; mt < 2; ++mt)
#pragma unroll
                    for (int nt = 0; nt < 4; ++nt) {
                        IMMA16832(hi[mt][nt], a1f[mt], b1f[nt]);
                        IMMA16832(mi[mt][nt], a1f[mt], b0f[nt]);
                        IMMA16832(mi[mt][nt], a0f[mt], b1f[nt]);
                    }
            }
            if (lane == 0) MBAR_ARRIVE(sb + s * 16 + 8);

            if (tid == 0 && cc + STAGES < totalcc) {
                MBAR_WAIT(sb + s * 16 + 8, par);
                produce_chunk(sb, bid, cc + STAGES);
            }
        }

        // epilogue: x = sA*sB*(hi*65536 + mi*256) + bias; acc += V*tanh(x)
#pragma unroll
        for (int mt = 0; mt < 2; ++mt) {
            float p0 = 0.f, p1 = 0.f;
#pragma unroll
            for (int nt = 0; nt < 4; ++nt) {
                int nl = wn * 32 + nt * 8 + 2 * (lane & 3);
                float4 c0 = sBVS[nl], c1 = sBVS[nl + 1];
                float s00 = sAr[mt][0] * c0.z, s01 = sAr[mt][0] * c1.z;
                float s10 = sAr[mt][1] * c0.z, s11 = sAr[mt][1] * c1.z;
                float v0 = fmaf((float)hi[mt][nt][0], 65536.f, (float)mi[mt][nt][0] * 256.f);
                float v1 = fmaf((float)hi[mt][nt][1], 65536.f, (float)mi[mt][nt][1] * 256.f);
                float v2 = fmaf((float)hi[mt][nt][2], 65536.f, (float)mi[mt][nt][2] * 256.f);
                float v3 = fmaf((float)hi[mt][nt][3], 65536.f, (float)mi[mt][nt][3] * 256.f);
                p0 = fmaf(c0.y, tanh_fast(fmaf(v0, s00, c0.x)), p0);
                p0 = fmaf(c1.y, tanh_fast(fmaf(v1, s01, c1.x)), p0);
                p1 = fmaf(c0.y, tanh_fast(fmaf(v2, s10, c0.x)), p1);
                p1 = fmaf(c1.y, tanh_fast(fmaf(v3, s11, c1.x)), p1);
            }
            p0 += __shfl_xor_sync(0xFFFFFFFFu, p0, 1);
            p0 += __shfl_xor_sync(0xFFFFFFFFu, p0, 2);
            p1 += __shfl_xor_sync(0xFFFFFFFFu, p1, 1);
            p1 += __shfl_xor_sync(0xFFFFFFFFu, p1, 2);
            if ((lane & 3) == 0) {
                int r = wm * 32 + mt * 16 + (lane >> 2);
                red[r * 4 + wn]       = p0;
                red[(r + 8) * 4 + wn] = p1;
            }
        }
        __syncthreads();
        if (tid < 128)
            g_part[nb][m0 + tid] = (red[tid * 4] + red[tid * 4 + 1]) +
                                   (red[tid * 4 + 2] + red[tid * 4 + 3]);
        __syncthreads();
    }
}

// ---------------- kernel 4: mask + softmax + argmax + gather ----------------
__global__ void softmax_kernel(const float* __restrict__ value,
                               const int* __restrict__ mask,
                               float* __restrict__ ctx_out,
                               float* __restrict__ a_out) {
    const int b = blockIdx.x;
    const int tid = threadIdx.x;                  // 256
    __shared__ float smax[256];
    __shared__ int   sidx[256];
    __shared__ float ssum[256];
    __shared__ float sc[T_];

    float m = -INFINITY; int mi = T_;
    for (int t = tid; t < T_; t += 256) {
        int i = b * T_ + t;
        float s = g_part[0][i] + g_part[1][i] + g_part[2][i] + g_part[3][i] +
                  (1.f - (float)mask[i]) * -1e20f;
        sc[t] = s;
        if (s > m) { m = s; mi = t; }
    }
    smax[tid] = m; sidx[tid] = mi;
    __syncthreads();
    for (int s = 128; s > 0; s >>= 1) {
        if (tid < s) {
            float om = smax[tid + s]; int oi = sidx[tid + s];
            if (om > smax[tid] || (om == smax[tid] && oi < sidx[tid])) {
                smax[tid] = om; sidx[tid] = oi;
            }
        }
        __syncthreads();
    }
    const float gmax = smax[0];
    const int gidx = sidx[0];

    float sum = 0.f;
    for (int t = tid; t < T_; t += 256) {
        float e = expf(sc[t] - gmax);
        sc[t] = e;
        sum += e;
    }
    ssum[tid] = sum;
    __syncthreads();
    for (int s = 128; s > 0; s >>= 1) {
        if (tid < s) ssum[tid] += ssum[tid + s];
        __syncthreads();
    }
    const float inv = 1.f / ssum[0];

    for (int t = tid; t < T_; t += 256) a_out[b * T_ + t] = sc[t] * inv;
    for (int d = tid; d < D_; d += 256)
        ctx_out[b * D_ + d] = value[((size_t)b * T_ + gidx) * D_ + d];
}

// ---------------------------------------------------------------------------
extern "C" void kernel_launch(void* const* d_in, const int* in_sizes, int n_in,
                              void* d_out, int out_size) {
    const float* value = (const float*)d_in[0];
    const float* query = (const float*)d_in[1];
    const int*   mask  = (const int*)d_in[2];
    const float* W1    = (const float*)d_in[3];
    const float* W2    = (const float*)d_in[4];
    const float* V     = (const float*)d_in[5];

    float* ctx = (float*)d_out;
    float* a   = (float*)d_out + B_ * D_;

    cudaFuncSetAttribute(score_mma_kernel,
                         cudaFuncAttributeMaxDynamicSharedMemorySize, SMEM_TOTAL);
    cudaFuncSetAttribute(convert_w1t,
                         cudaFuncAttributeMaxDynamicSharedMemorySize,
                         512 * 33 * (int)sizeof(float));

    convert_value<<<MT / 8, 256>>>((const float4*)value);
    convert_w1t<<<U_ / 32, 256, 512 * 33 * sizeof(float)>>>(W1);
    bias_part_kernel<<<dim3(B_, KSPLIT), U_>>>(query, W2);
    score_mma_kernel<<<GRID_P, 512, SMEM_TOTAL>>>(V);
    softmax_kernel<<<B_, 256>>>(value, mask, ctx, a);
}

// round 12
// speedup vs baseline: 2.4103x; 2.4103x over previous
#include <cuda_runtime.h>
#include <cuda_bf16.h>
#include <math.h>
#include <stdint.h>

#define B_ 32
#define T_ 2048
#define D_ 512
#define U_ 512
#define MT 65536            // B*T rows
#define MB_ 512             // M blocks of 128
#define NB_ 4               // N blocks of 128
#define KCH 8               // k chunks of 64
#define STAGES 3
#define KSPLIT 8
#define TILE_BYTES 16384    // 128 x 64 bf16
#define GRID_P 148          // persistent CTAs (1 per SM)
#define NTILES (MB_ * NB_)  // 2048

// ---------------- scratch (static device memory only) -----------------------
__device__ __align__(128) __nv_bfloat16 g_val_hi[MT * D_];
__device__ __align__(128) __nv_bfloat16 g_val_lo[MT * D_];
__device__ __align__(128) __nv_bfloat16 g_w1t_hi[U_ * D_];
__device__ __align__(128) __nv_bfloat16 g_w1t_lo[U_ * D_];
__device__ float g_bias_part[KSPLIT][B_ * U_];
__device__ float g_part[NB_][MT];

// ---------------- PTX helpers -----------------------------------------------
__device__ __forceinline__ uint32_t smem_u32(const void* p) {
    uint32_t a;
    asm("{ .reg .u64 t; cvta.to.shared.u64 t, %1; cvt.u32.u64 %0, t; }"
        : "=r"(a) : "l"(p));
    return a;
}
__device__ __forceinline__ uint32_t sw128(uint32_t off) {
    return off ^ ((off >> 3) & 0x70);
}
#define MBAR_INIT(a, n) \
    asm volatile("mbarrier.init.shared.b64 [%0], %1;" :: "r"(a), "r"(n) : "memory")
#define MBAR_ARRIVE(a) \
    asm volatile("mbarrier.arrive.shared.b64 _, [%0];" :: "r"(a) : "memory")
#define MBAR_EXPECT_TX(a, n) \
    asm volatile("mbarrier.arrive.expect_tx.shared.b64 _, [%0], %1;" \
                 :: "r"(a), "r"(n) : "memory")
#define MBAR_WAIT(a, ph) do {                                                  \
    uint32_t _m = (a), _p = (ph), _d;                                          \
    asm volatile("{ .reg .pred p; mbarrier.try_wait.parity.acquire.cta.shared::cta.b64 p, [%1], %2; selp.b32 %0,1,0,p; }" \
                 : "=r"(_d) : "r"(_m), "r"(_p) : "memory");                    \
    if (!_d) {                                                                 \
        asm volatile("{ .reg .pred P1; WL%=: mbarrier.try_wait.parity.acquire.cta.shared::cta.b64 P1, [%0], %1, 0x989680; @P1 bra.uni WD%=; bra.uni WL%=; WD%=: }" \
                     :: "r"(_m), "r"(_p) : "memory");                          \
    }                                                                          \
} while (0)
#define BULK_G2S(dst, src, bytes, mbar)                                        \
    asm volatile("cp.async.bulk.shared::cluster.global.mbarrier::complete_tx::bytes [%0], [%1], %2, [%3];" \
                 :: "r"(dst), "l"(src), "r"(bytes), "r"(mbar) : "memory")
#define LDSM4(r, addr)                                                         \
    asm volatile("ldmatrix.sync.aligned.m8n8.x4.shared.b16 {%0,%1,%2,%3}, [%4];" \
                 : "=r"((r)[0]), "=r"((r)[1]), "=r"((r)[2]), "=r"((r)[3])      \
                 : "r"(addr))
#define MMA16816(d, a, b)                                                      \
    asm volatile("mma.sync.aligned.m16n8k16.row.col.f32.bf16.bf16.f32 "        \
                 "{%0,%1,%2,%3}, {%4,%5,%6,%7}, {%8,%9}, {%0,%1,%2,%3};"       \
                 : "+f"((d)[0]), "+f"((d)[1]), "+f"((d)[2]), "+f"((d)[3])      \
                 : "r"((a)[0]), "r"((a)[1]), "r"((a)[2]), "r"((a)[3]),         \
                   "r"((b)[0]), "r"((b)[1]))

// tanh via exp: abs err ~1e-6; saturates correctly for large |x|
__device__ __forceinline__ float tanh_fast(float x) {
    float z = __expf(2.0f * x);
    return 1.0f - __fdividef(2.0f, z + 1.0f);
}

// ---------------- kernel 1a: value fp32 -> tiled swizzled bf16 hi/lo --------
__global__ void convert_value(const float4* __restrict__ v4) {
    char* dhi = reinterpret_cast<char*>(g_val_hi);
    char* dlo = reinterpret_cast<char*>(g_val_lo);
    const int ngran = MT * D_ / 8;
    for (int i = blockIdx.x * blockDim.x + threadIdx.x; i < ngran;
         i += gridDim.x * blockDim.x) {
        int m  = i >> 6;
        int g8 = i & 63;
        float4 a = v4[m * 128 + g8 * 2];
        float4 b = v4[m * 128 + g8 * 2 + 1];
        float f[8] = {a.x, a.y, a.z, a.w, b.x, b.y, b.z, b.w};
        uint32_t hi[4], lo[4];
#pragma unroll
        for (int j = 0; j < 4; ++j) {
            __nv_bfloat16 h0 = __float2bfloat16(f[2 * j]);
            __nv_bfloat16 h1 = __float2bfloat16(f[2 * j + 1]);
            __nv_bfloat16 l0 = __float2bfloat16(f[2 * j] - __bfloat162float(h0));
            __nv_bfloat16 l1 = __float2bfloat16(f[2 * j + 1] - __bfloat162float(h1));
            __nv_bfloat162 th = __halves2bfloat162(h0, h1);
            __nv_bfloat162 tl = __halves2bfloat162(l0, l1);
            hi[j] = *reinterpret_cast<uint32_t*>(&th);
            lo[j] = *reinterpret_cast<uint32_t*>(&tl);
        }
        int mb = m >> 7, r = m & 127;
        int kc = g8 >> 3, cg = g8 & 7;
        size_t dest = (size_t)(mb * KCH + kc) * TILE_BYTES +
                      sw128((uint32_t)(r * 128 + cg * 16));
        *reinterpret_cast<uint4*>(dhi + dest) = make_uint4(hi[0], hi[1], hi[2], hi[3]);
        *reinterpret_cast<uint4*>(dlo + dest) = make_uint4(lo[0], lo[1], lo[2], lo[3]);
    }
}

// ---------------- kernel 1b: W1 [k][u] -> transposed tiled swizzled ---------
__global__ void convert_w1t(const float* __restrict__ W1) {
    __shared__ float s[32][33];
    const int u0 = blockIdx.x * 32, k0 = blockIdx.y * 32;
    const int tx = threadIdx.x, ty = threadIdx.y;      // (32, 4)
#pragma unroll
    for (int j = 0; j < 8; ++j)
        s[ty + 4 * j][tx] = W1[(size_t)(k0 + ty + 4 * j) * U_ + u0 + tx];
    __syncthreads();
    float f[8];
#pragma unroll
    for (int e = 0; e < 8; ++e) f[e] = s[ty * 8 + e][tx];
    uint32_t hi[4], lo[4];
#pragma unroll
    for (int j = 0; j < 4; ++j) {
        __nv_bfloat16 h0 = __float2bfloat16(f[2 * j]);
        __nv_bfloat16 h1 = __float2bfloat16(f[2 * j + 1]);
        __nv_bfloat16 l0 = __float2bfloat16(f[2 * j] - __bfloat162float(h0));
        __nv_bfloat16 l1 = __float2bfloat16(f[2 * j + 1] - __bfloat162float(h1));
        __nv_bfloat162 th = __halves2bfloat162(h0, h1);
        __nv_bfloat162 tl = __halves2bfloat162(l0, l1);
        hi[j] = *reinterpret_cast<uint32_t*>(&th);
        lo[j] = *reinterpret_cast<uint32_t*>(&tl);
    }
    int u = u0 + tx, kk = k0 + ty * 8;
    int nb = u >> 7, r = u & 127;
    int kc = kk >> 6, cg = (kk & 63) >> 3;
    size_t dest = (size_t)(nb * KCH + kc) * TILE_BYTES +
                  sw128((uint32_t)(r * 128 + cg * 16));
    *reinterpret_cast<uint4*>(reinterpret_cast<char*>(g_w1t_hi) + dest) =
        make_uint4(hi[0], hi[1], hi[2], hi[3]);
    *reinterpret_cast<uint4*>(reinterpret_cast<char*>(g_w1t_lo) + dest) =
        make_uint4(lo[0], lo[1], lo[2], lo[3]);
}

// ---------------- kernel 2: bias partials (split-K, deterministic) ----------
__global__ void bias_part_kernel(const float* __restrict__ q,
                                 const float* __restrict__ W2) {
    const int b = blockIdx.x, ks = blockIdx.y, u = threadIdx.x;
    const float* qb = q + b * D_;
    float acc = 0.f;
#pragma unroll 4
    for (int d = ks * (D_ / KSPLIT); d < (ks + 1) * (D_ / KSPLIT); ++d)
        acc = fmaf(qb[d], W2[(size_t)d * U_ + u], acc);
    g_bias_part[ks][b * U_ + u] = acc;
}

// ---------------- kernel 3: persistent HMMA GEMM + fused epilogue -----------
// grid = 148.  512 threads = 16 warps (wm 0-3 x wn 0-3), warp tile 32x32.
// 3-stage bulk pipeline across tiles; register double-buffered fragments so
// LDSM latency hides behind the previous kk-step's 24 HMMA issues.
#define SM_DATA 4096
#define STG_SZ 65536
#define SMEM_TOTAL (SM_DATA + STAGES * STG_SZ)

static __device__ __forceinline__ void produce_chunk(uint32_t sb, int bid, int cc) {
    const int t  = bid + (cc >> 3) * GRID_P;
    const int mb = t >> 2, nb = t & 3, c = cc & 7;
    const int s  = cc % STAGES;
    const uint32_t st = sb + SM_DATA + s * STG_SZ;
    const size_t offA = (size_t)(mb * KCH + c) * TILE_BYTES;
    const size_t offB = (size_t)(nb * KCH + c) * TILE_BYTES;
    MBAR_EXPECT_TX(sb + s * 16, 4 * TILE_BYTES);
    BULK_G2S(st,         reinterpret_cast<const char*>(g_val_hi) + offA, TILE_BYTES, sb + s * 16);
    BULK_G2S(st + 16384, reinterpret_cast<const char*>(g_val_lo) + offA, TILE_BYTES, sb + s * 16);
    BULK_G2S(st + 32768, reinterpret_cast<const char*>(g_w1t_hi) + offB, TILE_BYTES, sb + s * 16);
    BULK_G2S(st + 49152, reinterpret_cast<const char*>(g_w1t_lo) + offB, TILE_BYTES, sb + s * 16);
}

__global__ void __launch_bounds__(512, 1)
score_mma_kernel(const float* __restrict__ Vw) {
    extern __shared__ char smem[];
    const uint32_t sb = smem_u32(smem);
    const int tid = threadIdx.x;
    const int lane = tid & 31, wid = tid >> 5;
    const int wm = wid >> 2, wn = wid & 3;
    const int bid = blockIdx.x;

    const int ntiles  = (NTILES - bid + GRID_P - 1) / GRID_P;
    const int totalcc = ntiles * KCH;

    if (tid == 0) {
#pragma unroll
        for (int s = 0; s < STAGES; ++s) {
            MBAR_INIT(sb + s * 16, 1);        // full: expect_tx arrival
            MBAR_INIT(sb + s * 16 + 8, 16);   // empty: one lane per warp
        }
    }
    __syncthreads();

    if (tid == 0) {
#pragma unroll
        for (int c = 0; c < STAGES; ++c)
            if (c < totalcc) produce_chunk(sb, bid, c);
    }

    // hoisted swizzle components: addr = stage + row*128 + (colbyte ^ xormask)
    uint32_t rowA[2], xmA[2], rowB[2], xmB[2];
#pragma unroll
    for (int mt = 0; mt < 2; ++mt) {
        rowA[mt] = (uint32_t)((wm * 32 + mt * 16 + (lane & 15)) * 128);
        xmA[mt]  = (rowA[mt] >> 3) & 0x70;
    }
#pragma unroll
    for (int p = 0; p < 2; ++p) {
        rowB[p] = (uint32_t)((wn * 32 + p * 16 + (lane & 15)) * 128);
        xmB[p]  = (rowB[p] >> 3) & 0x70;
    }
    const uint32_t hi16 = (uint32_t)(((lane >> 4) & 1) * 16);

    float2* sBV = reinterpret_cast<float2*>(smem + 64);
    float* red  = reinterpret_cast<float*>(smem + 1088);   // [128][4]

    // double-buffered fragments
    uint32_t ah[2][2][4], al[2][2][4], bh[2][4][2], bl[2][4][2];

    int cc = 0;
    for (int j = 0; j < ntiles; ++j) {
        const int t  = bid + j * GRID_P;
        const int mb = t >> 2, nb = t & 3;
        const int m0 = mb * 128;
        const int b  = mb >> 4;

        for (int i = tid; i < 128; i += 512) {
            int u = nb * 128 + i;
            float bs = 0.f;
#pragma unroll
            for (int jj = 0; jj < KSPLIT; ++jj) bs += g_bias_part[jj][b * U_ + u];
            sBV[i] = make_float2(bs, Vw[u]);
        }
        __syncthreads();

        float acc[2][4][4];
#pragma unroll
        for (int mt = 0; mt < 2; ++mt)
#pragma unroll
            for (int nt = 0; nt < 4; ++nt)
#pragma unroll
                for (int e = 0; e < 4; ++e) acc[mt][nt][e] = 0.f;

#pragma unroll
        for (int c = 0; c < KCH; ++c, ++cc) {
            const int s = cc % STAGES;
            const uint32_t par = (uint32_t)((cc / STAGES) & 1);
            MBAR_WAIT(sb + s * 16, par);

            const uint32_t aBase = sb + SM_DATA + s * STG_SZ;
            const uint32_t bBase = aBase + 32768;

            // prime buffer 0 with kk=0 fragments
            {
                const uint32_t col = hi16;
#pragma unroll
                for (int mt = 0; mt < 2; ++mt) {
                    uint32_t ad = aBase + rowA[mt] + (col ^ xmA[mt]);
                    LDSM4(ah[0][mt], ad);
                    LDSM4(al[0][mt], ad + 16384);
                }
#pragma unroll
                for (int p = 0; p < 2; ++p) {
                    uint32_t bd = bBase + rowB[p] + (col ^ xmB[p]);
                    uint32_t r[4];
                    LDSM4(r, bd);
                    bh[0][2 * p][0] = r[0]; bh[0][2 * p + 1][0] = r[1];
                    bh[0][2 * p][1] = r[2]; bh[0][2 * p + 1][1] = r[3];
                    LDSM4(r, bd + 16384);
                    bl[0][2 * p][0] = r[0]; bl[0][2 * p + 1][0] = r[1];
                    bl[0][2 * p][1] = r[2]; bl[0][2 * p + 1][1] = r[3];
                }
            }

#pragma unroll
            for (int kk = 0; kk < 4; ++kk) {
                const int cur = kk & 1, nxt = cur ^ 1;
                if (kk < 3) {       // prefetch kk+1 fragments before the MMAs
                    const uint32_t col = (uint32_t)((kk + 1) * 32) + hi16;
#pragma unroll
                    for (int mt = 0; mt < 2; ++mt) {
                        uint32_t ad = aBase + rowA[mt] + (col ^ xmA[mt]);
                        LDSM4(ah[nxt][mt], ad);
                        LDSM4(al[nxt][mt], ad + 16384);
                    }
#pragma unroll
                    for (int p = 0; p < 2; ++p) {
                        uint32_t bd = bBase + rowB[p] + (col ^ xmB[p]);
                        uint32_t r[4];
                        LDSM4(r, bd);
                        bh[nxt][2 * p][0] = r[0]; bh[nxt][2 * p + 1][0] = r[1];
                        bh[nxt][2 * p][1] = r[2]; bh[nxt][2 * p + 1][1] = r[3];
                        LDSM4(r, bd + 16384);
                        bl[nxt][2 * p][0] = r[0]; bl[nxt][2 * p + 1][0] = r[1];
                        bl[nxt][2 * p][1] = r[2]; bl[nxt][2 * p + 1][1] = r[3];
                    }
                }
#pragma unroll
                for (int mt = 0; mt < 2; ++mt)
#pragma unroll
                    for (int nt = 0; nt < 4; ++nt) {
                        MMA16816(acc[mt][nt], ah[cur][mt], bh[cur][nt]);
                        MMA16816(acc[mt][nt], ah[cur][mt], bl[cur][nt]);
                        MMA16816(acc[mt][nt], al[cur][mt], bh[cur][nt]);
                    }
            }
            if (lane == 0) MBAR_ARRIVE(sb + s * 16 + 8);

            if (tid == 0 && cc + STAGES < totalcc) {
                MBAR_WAIT(sb + s * 16 + 8, par);
                produce_chunk(sb, bid, cc + STAGES);
            }
        }

        // epilogue: V[u]*tanh(c + bias[u]); reduce across lanes + wn
#pragma unroll
        for (int mt = 0; mt < 2; ++mt) {
            float p0 = 0.f, p1 = 0.f;
#pragma unroll
            for (int nt = 0; nt < 4; ++nt) {
                int nl = wn * 32 + nt * 8 + 2 * (lane & 3);
                float2 bv0 = sBV[nl], bv1 = sBV[nl + 1];
                p0 = fmaf(bv0.y, tanh_fast(acc[mt][nt][0] + bv0.x), p0);
                p0 = fmaf(bv1.y, tanh_fast(acc[mt][nt][1] + bv1.x), p0);
                p1 = fmaf(bv0.y, tanh_fast(acc[mt][nt][2] + bv0.x), p1);
                p1 = fmaf(bv1.y, tanh_fast(acc[mt][nt][3] + bv1.x), p1);
            }
            p0 += __shfl_xor_sync(0xFFFFFFFFu, p0, 1);
            p0 += __shfl_xor_sync(0xFFFFFFFFu, p0, 2);
            p1 += __shfl_xor_sync(0xFFFFFFFFu, p1, 1);
            p1 += __shfl_xor_sync(0xFFFFFFFFu, p1, 2);
            if ((lane & 3) == 0) {
                int r = wm * 32 + mt * 16 + (lane >> 2);
                red[r * 4 + wn]       = p0;
                red[(r + 8) * 4 + wn] = p1;
            }
        }
        __syncthreads();
        if (tid < 128)
            g_part[nb][m0 + tid] = (red[tid * 4] + red[tid * 4 + 1]) +
                                   (red[tid * 4 + 2] + red[tid * 4 + 3]);
        __syncthreads();
    }
}

// ---------------- kernel 4: mask + softmax + argmax + gather ----------------
__global__ void softmax_kernel(const float* __restrict__ value,
                               const int* __restrict__ mask,
                               float* __restrict__ ctx_out,
                               float* __restrict__ a_out) {
    const int b = blockIdx.x;
    const int tid = threadIdx.x;                  // 256
    __shared__ float smax[256];
    __shared__ int   sidx[256];
    __shared__ float ssum[256];
    __shared__ float sc[T_];

    float m = -INFINITY; int mi = T_;
    for (int t = tid; t < T_; t += 256) {
        int i = b * T_ + t;
        float s = g_part[0][i] + g_part[1][i] + g_part[2][i] + g_part[3][i] +
                  (1.f - (float)mask[i]) * -1e20f;
        sc[t] = s;
        if (s > m) { m = s; mi = t; }
    }
    smax[tid] = m; sidx[tid] = mi;
    __syncthreads();
    for (int s = 128; s > 0; s >>= 1) {
        if (tid < s) {
            float om = smax[tid + s]; int oi = sidx[tid + s];
            if (om > smax[tid] || (om == smax[tid] && oi < sidx[tid])) {
                smax[tid] = om; sidx[tid] = oi;
            }
        }
        __syncthreads();
    }
    const float gmax = smax[0];
    const int gidx = sidx[0];

    float sum = 0.f;
    for (int t = tid; t < T_; t += 256) {
        float e = expf(sc[t] - gmax);
        sc[t] = e;
        sum += e;
    }
    ssum[tid] = sum;
    __syncthreads();
    for (int s = 128; s > 0; s >>= 1) {
        if (tid < s) ssum[tid] += ssum[tid + s];
        __syncthreads();
    }
    const float inv = 1.f / ssum[0];

    for (int t = tid; t < T_; t += 256) a_out[b * T_ + t] = sc[t] * inv;
    for (int d = tid; d < D_; d += 256)
        ctx_out[b * D_ + d] = value[((size_t)b * T_ + gidx) * D_ + d];
}

// ---------------------------------------------------------------------------
extern "C" void kernel_launch(void* const* d_in, const int* in_sizes, int n_in,
                              void* d_out, int out_size) {
    const float* value = (const float*)d_in[0];
    const float* query = (const float*)d_in[1];
    const int*   mask  = (const int*)d_in[2];
    const float* W1    = (const float*)d_in[3];
    const float* W2    = (const float*)d_in[4];
    const float* V     = (const float*)d_in[5];

    float* ctx = (float*)d_out;
    float* a   = (float*)d_out + B_ * D_;

    cudaFuncSetAttribute(score_mma_kernel,
                         cudaFuncAttributeMaxDynamicSharedMemorySize, SMEM_TOTAL);

    convert_value<<<2048, 256>>>((const float4*)value);
    convert_w1t<<<dim3(U_ / 32, D_ / 32), dim3(32, 4)>>>(W1);
    bias_part_kernel<<<dim3(B_, KSPLIT), U_>>>(query, W2);
    score_mma_kernel<<<GRID_P, 512, SMEM_TOTAL>>>(V);
    softmax_kernel<<<B_, 256>>>(value, mask, ctx, a);
}

// round 16
// speedup vs baseline: 2.4573x; 1.0195x over previous
#include <cuda_runtime.h>
#include <cuda_fp16.h>
#include <math.h>
#include <stdint.h>

#define B_ 32
#define T_ 2048
#define D_ 512
#define U_ 512
#define MT 65536            // B*T rows
#define MB_ 512             // M blocks of 128
#define NB_ 4               // N blocks of 128
#define KCH 8               // k chunks of 64
#define STAGES 3
#define KSPLIT 8
#define TILE_BYTES 16384    // 128 x 64 f16
#define GRID_P 148          // persistent CTAs (1 per SM)
#define NTILES (MB_ * NB_)  // 2048

// ---------------- scratch (static device memory only) -----------------------
// f16 hi/lo split: x = hi + lo/1024   (lo stored prescaled by 1024)
__device__ __align__(128) __half g_val_hi[MT * D_];
__device__ __align__(128) __half g_val_lo[MT * D_];
__device__ __align__(128) __half g_w1t_hi[U_ * D_];
__device__ __align__(128) __half g_w1t_lo[U_ * D_];
__device__ float g_bias_part[KSPLIT][B_ * U_];
__device__ float g_part[NB_][MT];

// ---------------- PTX helpers -----------------------------------------------
__device__ __forceinline__ uint32_t smem_u32(const void* p) {
    uint32_t a;
    asm("{ .reg .u64 t; cvta.to.shared.u64 t, %1; cvt.u32.u64 %0, t; }"
        : "=r"(a) : "l"(p));
    return a;
}
__device__ __forceinline__ uint32_t sw128(uint32_t off) {
    return off ^ ((off >> 3) & 0x70);
}
#define MBAR_INIT(a, n) \
    asm volatile("mbarrier.init.shared.b64 [%0], %1;" :: "r"(a), "r"(n) : "memory")
#define MBAR_ARRIVE(a) \
    asm volatile("mbarrier.arrive.shared.b64 _, [%0];" :: "r"(a) : "memory")
#define MBAR_EXPECT_TX(a, n) \
    asm volatile("mbarrier.arrive.expect_tx.shared.b64 _, [%0], %1;" \
                 :: "r"(a), "r"(n) : "memory")
#define MBAR_WAIT(a, ph) do {                                                  \
    uint32_t _m = (a), _p = (ph), _d;                                          \
    asm volatile("{ .reg .pred p; mbarrier.try_wait.parity.acquire.cta.shared::cta.b64 p, [%1], %2; selp.b32 %0,1,0,p; }" \
                 : "=r"(_d) : "r"(_m), "r"(_p) : "memory");                    \
    if (!_d) {                                                                 \
        asm volatile("{ .reg .pred P1; WL%=: mbarrier.try_wait.parity.acquire.cta.shared::cta.b64 P1, [%0], %1, 0x989680; @P1 bra.uni WD%=; bra.uni WL%=; WD%=: }" \
                     :: "r"(_m), "r"(_p) : "memory");                          \
    }                                                                          \
} while (0)
#define BULK_G2S(dst, src, bytes, mbar)                                        \
    asm volatile("cp.async.bulk.shared::cluster.global.mbarrier::complete_tx::bytes [%0], [%1], %2, [%3];" \
                 :: "r"(dst), "l"(src), "r"(bytes), "r"(mbar) : "memory")
#define LDSM4(r, addr)                                                         \
    asm volatile("ldmatrix.sync.aligned.m8n8.x4.shared.b16 {%0,%1,%2,%3}, [%4];" \
                 : "=r"((r)[0]), "=r"((r)[1]), "=r"((r)[2]), "=r"((r)[3])      \
                 : "r"(addr))
// main pass: f16 inputs, f32 accum
#define MMAF(d, a, b)                                                          \
    asm volatile("mma.sync.aligned.m16n8k16.row.col.f32.f16.f16.f32 "          \
                 "{%0,%1,%2,%3}, {%4,%5,%6,%7}, {%8,%9}, {%0,%1,%2,%3};"       \
                 : "+f"((d)[0]), "+f"((d)[1]), "+f"((d)[2]), "+f"((d)[3])      \
                 : "r"((a)[0]), "r"((a)[1]), "r"((a)[2]), "r"((a)[3]),         \
                   "r"((b)[0]), "r"((b)[1]))
// cross passes: f16 inputs, f16 accum (2 regs = 4 halves)
#define MMAH(d, a, b)                                                          \
    asm volatile("mma.sync.aligned.m16n8k16.row.col.f16.f16.f16.f16 "          \
                 "{%0,%1}, {%2,%3,%4,%5}, {%6,%7}, {%0,%1};"                   \
                 : "+r"((d)[0]), "+r"((d)[1])                                  \
                 : "r"((a)[0]), "r"((a)[1]), "r"((a)[2]), "r"((a)[3]),         \
                   "r"((b)[0]), "r"((b)[1]))

// tanh via exp: abs err ~1e-6; saturates correctly for large |x|
__device__ __forceinline__ float tanh_fast(float x) {
    float z = __expf(2.0f * x);
    return 1.0f - __fdividef(2.0f, z + 1.0f);
}

// ---------------- kernel 1a: value fp32 -> tiled swizzled f16 hi/lo ---------
__global__ void convert_value(const float4* __restrict__ v4) {
    char* dhi = reinterpret_cast<char*>(g_val_hi);
    char* dlo = reinterpret_cast<char*>(g_val_lo);
    const int ngran = MT * D_ / 8;
    for (int i = blockIdx.x * blockDim.x + threadIdx.x; i < ngran;
         i += gridDim.x * blockDim.x) {
        int m  = i >> 6;
        int g8 = i & 63;
        float4 a = v4[m * 128 + g8 * 2];
        float4 b = v4[m * 128 + g8 * 2 + 1];
        float f[8] = {a.x, a.y, a.z, a.w, b.x, b.y, b.z, b.w};
        uint32_t hi[4], lo[4];
#pragma unroll
        for (int j = 0; j < 4; ++j) {
            __half h0 = __float2half_rn(f[2 * j]);
            __half h1 = __float2half_rn(f[2 * j + 1]);
            __half l0 = __float2half_rn((f[2 * j]     - __half2float(h0)) * 1024.f);
            __half l1 = __float2half_rn((f[2 * j + 1] - __half2float(h1)) * 1024.f);
            __half2 th = __halves2half2(h0, h1);
            __half2 tl = __halves2half2(l0, l1);
            hi[j] = *reinterpret_cast<uint32_t*>(&th);
            lo[j] = *reinterpret_cast<uint32_t*>(&tl);
        }
        int mb = m >> 7, r = m & 127;
        int kc = g8 >> 3, cg = g8 & 7;
        size_t dest = (size_t)(mb * KCH + kc) * TILE_BYTES +
                      sw128((uint32_t)(r * 128 + cg * 16));
        *reinterpret_cast<uint4*>(dhi + dest) = make_uint4(hi[0], hi[1], hi[2], hi[3]);
        *reinterpret_cast<uint4*>(dlo + dest) = make_uint4(lo[0], lo[1], lo[2], lo[3]);
    }
}

// ---------------- kernel 1b: W1 [k][u] -> transposed tiled swizzled ---------
__global__ void convert_w1t(const float* __restrict__ W1) {
    __shared__ float s[32][33];
    const int u0 = blockIdx.x * 32, k0 = blockIdx.y * 32;
    const int tx = threadIdx.x, ty = threadIdx.y;      // (32, 4)
#pragma unroll
    for (int j = 0; j < 8; ++j)
        s[ty + 4 * j][tx] = W1[(size_t)(k0 + ty + 4 * j) * U_ + u0 + tx];
    __syncthreads();
    float f[8];
#pragma unroll
    for (int e = 0; e < 8; ++e) f[e] = s[ty * 8 + e][tx];
    uint32_t hi[4], lo[4];
#pragma unroll
    for (int j = 0; j < 4; ++j) {
        __half h0 = __float2half_rn(f[2 * j]);
        __half h1 = __float2half_rn(f[2 * j + 1]);
        __half l0 = __float2half_rn((f[2 * j]     - __half2float(h0)) * 1024.f);
        __half l1 = __float2half_rn((f[2 * j + 1] - __half2float(h1)) * 1024.f);
        __half2 th = __halves2half2(h0, h1);
        __half2 tl = __halves2half2(l0, l1);
        hi[j] = *reinterpret_cast<uint32_t*>(&th);
        lo[j] = *reinterpret_cast<uint32_t*>(&tl);
    }
    int u = u0 + tx, kk = k0 + ty * 8;
    int nb = u >> 7, r = u & 127;
    int kc = kk >> 6, cg = (kk & 63) >> 3;
    size_t dest = (size_t)(nb * KCH + kc) * TILE_BYTES +
                  sw128((uint32_t)(r * 128 + cg * 16));
    *reinterpret_cast<uint4*>(reinterpret_cast<char*>(g_w1t_hi) + dest) =
        make_uint4(hi[0], hi[1], hi[2], hi[3]);
    *reinterpret_cast<uint4*>(reinterpret_cast<char*>(g_w1t_lo) + dest) =
        make_uint4(lo[0], lo[1], lo[2], lo[3]);
}

// ---------------- kernel 2: bias partials (split-K, deterministic) ----------
__global__ void bias_part_kernel(const float* __restrict__ q,
                                 const float* __restrict__ W2) {
    const int b = blockIdx.x, ks = blockIdx.y, u = threadIdx.x;
    const float* qb = q + b * D_;
    float acc = 0.f;
#pragma unroll 4
    for (int d = ks * (D_ / KSPLIT); d < (ks + 1) * (D_ / KSPLIT); ++d)
        acc = fmaf(qb[d], W2[(size_t)d * U_ + u], acc);
    g_bias_part[ks][b * U_ + u] = acc;
}

// ---------------- kernel 3: persistent GEMM + fused epilogue ----------------
// grid = 148.  512 threads = 16 warps (wm 0-3 x wn 0-3), warp tile 32x32.
// Passes: ah*bh (f32 accum), ah*bl + al*bh (f16 accum, x1024 prescale).
#define SM_DATA 4096
#define STG_SZ 65536
#define SMEM_TOTAL (SM_DATA + STAGES * STG_SZ)

static __device__ __forceinline__ void produce_chunk(uint32_t sb, int bid, int cc) {
    const int t  = bid + (cc >> 3) * GRID_P;
    const int mb = t >> 2, nb = t & 3, c = cc & 7;
    const int s  = cc % STAGES;
    const uint32_t st = sb + SM_DATA + s * STG_SZ;
    const size_t offA = (size_t)(mb * KCH + c) * TILE_BYTES;
    const size_t offB = (size_t)(nb * KCH + c) * TILE_BYTES;
    MBAR_EXPECT_TX(sb + s * 16, 4 * TILE_BYTES);
    BULK_G2S(st,         reinterpret_cast<const char*>(g_val_hi) + offA, TILE_BYTES, sb + s * 16);
    BULK_G2S(st + 16384, reinterpret_cast<const char*>(g_val_lo) + offA, TILE_BYTES, sb + s * 16);
    BULK_G2S(st + 32768, reinterpret_cast<const char*>(g_w1t_hi) + offB, TILE_BYTES, sb + s * 16);
    BULK_G2S(st + 49152, reinterpret_cast<const char*>(g_w1t_lo) + offB, TILE_BYTES, sb + s * 16);
}

__global__ void __launch_bounds__(512, 1)
score_mma_kernel(const float* __restrict__ Vw) {
    extern __shared__ char smem[];
    const uint32_t sb = smem_u32(smem);
    const int tid = threadIdx.x;
    const int lane = tid & 31, wid = tid >> 5;
    const int wm = wid >> 2, wn = wid & 3;
    const int bid = blockIdx.x;

    const int ntiles  = (NTILES - bid + GRID_P - 1) / GRID_P;
    const int totalcc = ntiles * KCH;

    if (tid == 0) {
#pragma unroll
        for (int s = 0; s < STAGES; ++s) {
            MBAR_INIT(sb + s * 16, 1);        // full: expect_tx arrival
            MBAR_INIT(sb + s * 16 + 8, 16);   // empty: one lane per warp
        }
    }
    __syncthreads();

    if (tid == 0) {
#pragma unroll
        for (int c = 0; c < STAGES; ++c)
            if (c < totalcc) produce_chunk(sb, bid, c);
    }

    uint32_t rowA[2], xmA[2], rowB[2], xmB[2];
#pragma unroll
    for (int mt = 0; mt < 2; ++mt) {
        rowA[mt] = (uint32_t)((wm * 32 + mt * 16 + (lane & 15)) * 128);
        xmA[mt]  = (rowA[mt] >> 3) & 0x70;
    }
#pragma unroll
    for (int p = 0; p < 2; ++p) {
        rowB[p] = (uint32_t)((wn * 32 + p * 16 + (lane & 15)) * 128);
        xmB[p]  = (rowB[p] >> 3) & 0x70;
    }
    const uint32_t hi16 = (uint32_t)(((lane >> 4) & 1) * 16);

    float2* sBV = reinterpret_cast<float2*>(smem + 64);
    float* red  = reinterpret_cast<float*>(smem + 1088);   // [128][4]

    int cc = 0;
    for (int j = 0; j < ntiles; ++j) {
        const int t  = bid + j * GRID_P;
        const int mb = t >> 2, nb = t & 3;
        const int m0 = mb * 128;
        const int b  = mb >> 4;

        for (int i = tid; i < 128; i += 512) {
            int u = nb * 128 + i;
            float bs = 0.f;
#pragma unroll
            for (int jj = 0; jj < KSPLIT; ++jj) bs += g_bias_part[jj][b * U_ + u];
            sBV[i] = make_float2(bs, Vw[u]);
        }
        __syncthreads();

        float    accm[2][4][4];
        uint32_t accx[2][4][2];
#pragma unroll
        for (int mt = 0; mt < 2; ++mt)
#pragma unroll
            for (int nt = 0; nt < 4; ++nt) {
#pragma unroll
                for (int e = 0; e < 4; ++e) accm[mt][nt][e] = 0.f;
                accx[mt][nt][0] = 0u; accx[mt][nt][1] = 0u;
            }

#pragma unroll
        for (int c = 0; c < KCH; ++c, ++cc) {
            const int s = cc % STAGES;
            const uint32_t par = (uint32_t)((cc / STAGES) & 1);
            MBAR_WAIT(sb + s * 16, par);

            const uint32_t aBase = sb + SM_DATA + s * STG_SZ;
            const uint32_t bBase = aBase + 32768;
#pragma unroll
            for (int kk = 0; kk < 4; ++kk) {
                const uint32_t col = (uint32_t)(kk * 32) + hi16;
                uint32_t ah[2][4], al[2][4], bh[4][2], bl[4][2];
#pragma unroll
                for (int mt = 0; mt < 2; ++mt) {
                    uint32_t ad = aBase + rowA[mt] + (col ^ xmA[mt]);
                    LDSM4(ah[mt], ad);
                    LDSM4(al[mt], ad + 16384);
                }
#pragma unroll
                for (int p = 0; p < 2; ++p) {
                    uint32_t bd = bBase + rowB[p] + (col ^ xmB[p]);
                    uint32_t r[4];
                    LDSM4(r, bd);
                    bh[2 * p][0] = r[0]; bh[2 * p + 1][0] = r[1];
                    bh[2 * p][1] = r[2]; bh[2 * p + 1][1] = r[3];
                    LDSM4(r, bd + 16384);
                    bl[2 * p][0] = r[0]; bl[2 * p + 1][0] = r[1];
                    bl[2 * p][1] = r[2]; bl[2 * p + 1][1] = r[3];
                }
#pragma unroll
                for (int mt = 0; mt < 2; ++mt)
#pragma unroll
                    for (int nt = 0; nt < 4; ++nt) {
                        MMAF(accm[mt][nt], ah[mt], bh[nt]);
                        MMAH(accx[mt][nt], ah[mt], bl[nt]);
                        MMAH(accx[mt][nt], al[mt], bh[nt]);
                    }
            }
            if (lane == 0) MBAR_ARRIVE(sb + s * 16 + 8);

            if (tid == 0 && cc + STAGES < totalcc) {
                MBAR_WAIT(sb + s * 16 + 8, par);
                produce_chunk(sb, bid, cc + STAGES);
            }
        }

        // epilogue: x = main + cross/1024 + bias; acc += V*tanh(x)
        const float INV1024 = 9.765625e-4f;
#pragma unroll
        for (int mt = 0; mt < 2; ++mt) {
            float p0 = 0.f, p1 = 0.f;
#pragma unroll
            for (int nt = 0; nt < 4; ++nt) {
                int nl = wn * 32 + nt * 8 + 2 * (lane & 3);
                float2 bv0 = sBV[nl], bv1 = sBV[nl + 1];
                float2 c01 = __half22float2(*reinterpret_cast<__half2*>(&accx[mt][nt][0]));
                float2 c23 = __half22float2(*reinterpret_cast<__half2*>(&accx[mt][nt][1]));
                float x0 = fmaf(c01.x, INV1024, accm[mt][nt][0]) + bv0.x;
                float x1 = fmaf(c01.y, INV1024, accm[mt][nt][1]) + bv1.x;
                float x2 = fmaf(c23.x, INV1024, accm[mt][nt][2]) + bv0.x;
                float x3 = fmaf(c23.y, INV1024, accm[mt][nt][3]) + bv1.x;
                p0 = fmaf(bv0.y, tanh_fast(x0), p0);
                p0 = fmaf(bv1.y, tanh_fast(x1), p0);
                p1 = fmaf(bv0.y, tanh_fast(x2), p1);
                p1 = fmaf(bv1.y, tanh_fast(x3), p1);
            }
            p0 += __shfl_xor_sync(0xFFFFFFFFu, p0, 1);
            p0 += __shfl_xor_sync(0xFFFFFFFFu, p0, 2);
            p1 += __shfl_xor_sync(0xFFFFFFFFu, p1, 1);
            p1 += __shfl_xor_sync(0xFFFFFFFFu, p1, 2);
            if ((lane & 3) == 0) {
                int r = wm * 32 + mt * 16 + (lane >> 2);
                red[r * 4 + wn]       = p0;
                red[(r + 8) * 4 + wn] = p1;
            }
        }
        __syncthreads();
        if (tid < 128)
            g_part[nb][m0 + tid] = (red[tid * 4] + red[tid * 4 + 1]) +
                                   (red[tid * 4 + 2] + red[tid * 4 + 3]);
        __syncthreads();
    }
}

// ---------------- kernel 4: mask + softmax + argmax + gather ----------------
__global__ void softmax_kernel(const float* __restrict__ value,
                               const int* __restrict__ mask,
                               float* __restrict__ ctx_out,
                               float* __restrict__ a_out) {
    const int b = blockIdx.x;
    const int tid = threadIdx.x;                  // 256
    __shared__ float smax[256];
    __shared__ int   sidx[256];
    __shared__ float ssum[256];
    __shared__ float sc[T_];

    float m = -INFINITY; int mi = T_;
    for (int t = tid; t < T_; t += 256) {
        int i = b * T_ + t;
        float s = g_part[0][i] + g_part[1][i] + g_part[2][i] + g_part[3][i] +
                  (1.f - (float)mask[i]) * -1e20f;
        sc[t] = s;
        if (s > m) { m = s; mi = t; }
    }
    smax[tid] = m; sidx[tid] = mi;
    __syncthreads();
    for (int s = 128; s > 0; s >>= 1) {
        if (tid < s) {
            float om = smax[tid + s]; int oi = sidx[tid + s];
            if (om > smax[tid] || (om == smax[tid] && oi < sidx[tid])) {
                smax[tid] = om; sidx[tid] = oi;
            }
        }
        __syncthreads();
    }
    const float gmax = smax[0];
    const int gidx = sidx[0];

    float sum = 0.f;
    for (int t = tid; t < T_; t += 256) {
        float e = expf(sc[t] - gmax);
        sc[t] = e;
        sum += e;
    }
    ssum[tid] = sum;
    __syncthreads();
    for (int s = 128; s > 0; s >>= 1) {
        if (tid < s) ssum[tid] += ssum[tid + s];
        __syncthreads();
    }
    const float inv = 1.f / ssum[0];

    for (int t = tid; t < T_; t += 256) a_out[b * T_ + t] = sc[t] * inv;
    for (int d = tid; d < D_; d += 256)
        ctx_out[b * D_ + d] = value[((size_t)b * T_ + gidx) * D_ + d];
}

// ---------------------------------------------------------------------------
extern "C" void kernel_launch(void* const* d_in, const int* in_sizes, int n_in,
                              void* d_out, int out_size) {
    const float* value = (const float*)d_in[0];
    const float* query = (const float*)d_in[1];
    const int*   mask  = (const int*)d_in[2];
    const float* W1    = (const float*)d_in[3];
    const float* W2    = (const float*)d_in[4];
    const float* V     = (const float*)d_in[5];

    float* ctx = (float*)d_out;
    float* a   = (float*)d_out + B_ * D_;

    cudaFuncSetAttribute(score_mma_kernel,
                         cudaFuncAttributeMaxDynamicSharedMemorySize, SMEM_TOTAL);

    convert_value<<<2048, 256>>>((const float4*)value);
    convert_w1t<<<dim3(U_ / 32, D_ / 32), dim3(32, 4)>>>(W1);
    bias_part_kernel<<<dim3(B_, KSPLIT), U_>>>(query, W2);
    score_mma_kernel<<<GRID_P, 512, SMEM_TOTAL>>>(V);
    softmax_kernel<<<B_, 256>>>(value, mask, ctx, a);
}